// round 8
// baseline (speedup 1.0000x reference)
#include <cuda_runtime.h>
#include <cstdint>

#define NDIM 8192
#define THREADS 1024
#define NBLOCKS 148                 // persistent: one CTA per SM
#define DEPTH 4                     // ring depth (rows in flight per CTA)
#define ROWB 32768u                 // bytes per row (8192 fp32)
#define RING_BYTES (DEPTH * 32768)  // 128 KB ring
#define SMEM_TOTAL (RING_BYTES + 256)

// Scratch for deterministic final reduction (no cudaMalloc allowed).
__device__ float g_partA[NBLOCKS];
__device__ float g_partB[NBLOCKS];
__device__ int   g_count = 0;

// ---- packed f32x2 helpers (sm_103a) ----
__device__ __forceinline__ void fma2(unsigned long long& d,
                                     unsigned long long a,
                                     unsigned long long b) {
    asm("fma.rn.f32x2 %0, %1, %2, %0;" : "+l"(d) : "l"(a), "l"(b));
}
__device__ __forceinline__ void add2(unsigned long long& d,
                                     unsigned long long a) {
    asm("add.rn.f32x2 %0, %0, %1;" : "+l"(d) : "l"(a));
}
__device__ __forceinline__ float lo2(unsigned long long p) {
    unsigned int l, h;
    asm("mov.b64 {%0, %1}, %2;" : "=r"(l), "=r"(h) : "l"(p));
    return __uint_as_float(l);
}
__device__ __forceinline__ float hi2(unsigned long long p) {
    unsigned int l, h;
    asm("mov.b64 {%0, %1}, %2;" : "=r"(l), "=r"(h) : "l"(p));
    return __uint_as_float(h);
}

// ---- smem / mbarrier / bulk-copy helpers ----
__device__ __forceinline__ uint32_t smem_u32(const void* p) {
    uint32_t a;
    asm("{ .reg .u64 t; cvta.to.shared.u64 t, %1; cvt.u32.u64 %0, t; }"
        : "=r"(a) : "l"(p));
    return a;
}
__device__ __forceinline__ void mbar_init(uint32_t mbar, uint32_t cnt) {
    asm volatile("mbarrier.init.shared.b64 [%0], %1;" :: "r"(mbar), "r"(cnt) : "memory");
}
__device__ __forceinline__ void mbar_expect_tx(uint32_t mbar, uint32_t bytes) {
    asm volatile("mbarrier.arrive.expect_tx.shared.b64 _, [%0], %1;"
                 :: "r"(mbar), "r"(bytes) : "memory");
}
__device__ __forceinline__ void mbar_wait(uint32_t mbar, uint32_t parity) {
    asm volatile(
        "{\n\t.reg .pred P;\n\t"
        "W_%=:\n\t"
        "mbarrier.try_wait.parity.acquire.cta.shared::cta.b64 P, [%0], %1, 0x989680;\n\t"
        "@!P bra W_%=;\n\t}"
        :: "r"(mbar), "r"(parity) : "memory");
}
__device__ __forceinline__ void bulk_ld(uint32_t dst_smem, const void* src_gmem,
                                        uint32_t bytes, uint32_t mbar) {
    asm volatile(
        "cp.async.bulk.shared::cta.global.mbarrier::complete_tx::bytes "
        "[%0], [%1], %2, [%3];"
        :: "r"(dst_smem), "l"(src_gmem), "r"(bytes), "r"(mbar) : "memory");
}

extern __shared__ char dynsmem[];

__global__ __launch_bounds__(THREADS, 1)
void ising_fused(const float* __restrict__ M, const float* __restrict__ s,
                 float* __restrict__ out) {
    __shared__ float sA[THREADS / 32];
    __shared__ float sB[THREADS / 32];
    __shared__ int s_isLast;

    const int tid = threadIdx.x;
    const int lane = tid & 31;
    const int wid = tid >> 5;
    const int bid = blockIdx.x;

    const uint32_t ring = smem_u32(dynsmem);
    const uint32_t mbar0 = ring + RING_BYTES;      // DEPTH mbarriers, 8 B apart

    if (tid == 0) {
        #pragma unroll
        for (int d = 0; d < DEPTH; ++d) mbar_init(mbar0 + d * 8, 1);
    }
    __syncthreads();

    // Contiguous row partition: 8192 rows over 148 CTAs (55 or 56 each).
    const int rowBeg = (int)(((long long)bid * NDIM) / NBLOCKS);
    const int rowEnd = (int)(((long long)(bid + 1) * NDIM) / NBLOCKS);
    const int n = rowEnd - rowBeg;

    // This thread's fixed vec columns for every row.
    const int j4a = tid;             // in [0, 1024)
    const int j4b = tid + 1024;      // in [1024, 2048)

    // s slice lives in registers: loaded once, coalesced.
    const ulonglong2* s64g = reinterpret_cast<const ulonglong2*>(s);
    const ulonglong2 sa = __ldg(s64g + j4a);
    const ulonglong2 sb = __ldg(s64g + j4b);

    // Prime the ring.
    if (tid == 0) {
        #pragma unroll
        for (int k = 0; k < DEPTH; ++k) {
            if (k < n) {
                mbar_expect_tx(mbar0 + k * 8, ROWB);
                bulk_ld(ring + k * ROWB, M + (size_t)(rowBeg + k) * NDIM,
                        ROWB, mbar0 + k * 8);
            }
        }
    }

    unsigned long long a01 = 0ull, a23 = 0ull;   // packed plain sum
    float amAcc = 0.0f;                          // mixed-vec plain-sum remainder
    float bAcc  = 0.0f;                          // s_i-weighted upper-dot + diag

    #pragma unroll 1
    for (int k = 0; k < n; ++k) {
        const int slot = k & (DEPTH - 1);
        const uint32_t parity = (k >> 2) & 1;
        const int row = rowBeg + k;
        const int vs = row >> 2;

        mbar_wait(mbar0 + slot * 8, parity);

        const ulonglong2* m64 = reinterpret_cast<const ulonglong2*>(
            dynsmem + (size_t)slot * ROWB);
        const ulonglong2 v1 = m64[j4a];     // LDS.128
        const ulonglong2 v2 = m64[j4b];     // LDS.128
        const float srow = __ldg(s + row);  // uniform broadcast, L1-hot

        unsigned long long d01 = 0ull, d23 = 0ull;
        float dm = 0.0f;

        // --- vec 1 (j4a) ---
        if (j4a > vs) {
            add2(a01, v1.x);  add2(a23, v1.y);
            fma2(d01, v1.x, sa.x);  fma2(d23, v1.y, sa.y);
        } else if (j4a < vs) {
            add2(a01, v1.x);  add2(a23, v1.y);
        } else {
            const float vx = lo2(v1.x), vy = hi2(v1.x);
            const float vz = lo2(v1.y), vw = hi2(v1.y);
            const float tx = lo2(sa.x), ty = hi2(sa.x);
            const float tz = lo2(sa.y), tw = hi2(sa.y);
            const int j = j4a * 4;
            amAcc += (vx + vy) + (vz + vw);
            const float w0 = (j + 0 > row) ? tx : ((j + 0 == row) ? 1.0f : 0.0f);
            const float w1 = (j + 1 > row) ? ty : ((j + 1 == row) ? 1.0f : 0.0f);
            const float w2 = (j + 2 > row) ? tz : ((j + 2 == row) ? 1.0f : 0.0f);
            const float w3 = (j + 3 > row) ? tw : ((j + 3 == row) ? 1.0f : 0.0f);
            dm += fmaf(vx, w0, fmaf(vy, w1, fmaf(vz, w2, vw * w3)));
        }

        // --- vec 2 (j4b) ---
        if (j4b > vs) {
            add2(a01, v2.x);  add2(a23, v2.y);
            fma2(d01, v2.x, sb.x);  fma2(d23, v2.y, sb.y);
        } else if (j4b < vs) {
            add2(a01, v2.x);  add2(a23, v2.y);
        } else {
            const float vx = lo2(v2.x), vy = hi2(v2.x);
            const float vz = lo2(v2.y), vw = hi2(v2.y);
            const float tx = lo2(sb.x), ty = hi2(sb.x);
            const float tz = lo2(sb.y), tw = hi2(sb.y);
            const int j = j4b * 4;
            amAcc += (vx + vy) + (vz + vw);
            const float w0 = (j + 0 > row) ? tx : ((j + 0 == row) ? 1.0f : 0.0f);
            const float w1 = (j + 1 > row) ? ty : ((j + 1 == row) ? 1.0f : 0.0f);
            const float w2 = (j + 2 > row) ? tz : ((j + 2 == row) ? 1.0f : 0.0f);
            const float w3 = (j + 3 > row) ? tw : ((j + 3 == row) ? 1.0f : 0.0f);
            dm += fmaf(vx, w0, fmaf(vy, w1, fmaf(vz, w2, vw * w3)));
        }

        const float di = ((lo2(d01) + hi2(d01)) + (lo2(d23) + hi2(d23))) + dm;
        bAcc = fmaf(srow, di, bAcc);

        __syncthreads();   // all reads of this slot complete

        if (tid == 0 && k + DEPTH < n) {
            mbar_expect_tx(mbar0 + slot * 8, ROWB);
            bulk_ld(ring + slot * ROWB, M + (size_t)(row + DEPTH) * NDIM,
                    ROWB, mbar0 + slot * 8);
        }
    }

    float aAcc = ((lo2(a01) + hi2(a01)) + (lo2(a23) + hi2(a23))) + amAcc;

    // Warp shuffle reduction (deterministic).
    #pragma unroll
    for (int off = 16; off > 0; off >>= 1) {
        aAcc += __shfl_xor_sync(0xFFFFFFFFu, aAcc, off);
        bAcc += __shfl_xor_sync(0xFFFFFFFFu, bAcc, off);
    }
    if (lane == 0) { sA[wid] = aAcc; sB[wid] = bAcc; }
    __syncthreads();

    if (tid == 0) {
        float a = 0.f, b = 0.f;
        #pragma unroll
        for (int w = 0; w < THREADS / 32; ++w) { a += sA[w]; b += sB[w]; }
        g_partA[bid] = a;
        g_partB[bid] = b;
        __threadfence();
        const int prev = atomicAdd(&g_count, 1);
        s_isLast = (prev == (int)gridDim.x - 1);
    }
    __syncthreads();

    // Last block: deterministic final reduction in double (reuses ring smem).
    if (s_isLast) {
        double* rA = reinterpret_cast<double*>(dynsmem);
        double* rB = rA + THREADS;
        double a = (tid < NBLOCKS) ? (double)g_partA[tid] : 0.0;
        double b = (tid < NBLOCKS) ? (double)g_partB[tid] : 0.0;
        rA[tid] = a;
        rB[tid] = b;
        __syncthreads();
        #pragma unroll
        for (int st = THREADS / 2; st > 0; st >>= 1) {
            if (tid < st) { rA[tid] += rA[tid + st]; rB[tid] += rB[tid + st]; }
            __syncthreads();
        }
        if (tid == 0) {
            // out = sum(M)/4 - 0.5 * (sum_{i<j} M_ij s_i s_j + sum_i M_ii s_i)
            out[0] = (float)(rA[0] * 0.25 - 0.5 * rB[0]);
            g_count = 0;   // reset for next graph replay
        }
    }
}

extern "C" void kernel_launch(void* const* d_in, const int* in_sizes, int n_in,
                              void* d_out, int out_size) {
    const float* M = (const float*)d_in[0];   // info_mtx [8192, 8192] fp32
    const float* s = (const float*)d_in[1];   // state [8192] fp32
    float* out = (float*)d_out;

    cudaFuncSetAttribute(ising_fused,
                         cudaFuncAttributeMaxDynamicSharedMemorySize, SMEM_TOTAL);
    ising_fused<<<NBLOCKS, THREADS, SMEM_TOTAL>>>(M, s, out);
}